// round 3
// baseline (speedup 1.0000x reference)
#include <cuda_runtime.h>
#include <cuda_bf16.h>
#include <math.h>

// Problem constants
#define BB 2
#define TT 2048
#define CC 1024
#define HH 16
#define DD 64
#define CH 512
#define MM (BB*TT)   // 4096

// ---------------- scratch (static device allocs; no cudaMalloc allowed) ----
__device__ float g_h1[MM*CH];        // importance hidden
__device__ float g_xi[MM*CC];        // gated input
__device__ float g_rsnh[MM*CC];      // reasoning hidden
__device__ float g_reasoned[MM*CC];
__device__ float g_q[MM*CC];
__device__ float g_k[MM*CC];
__device__ float g_v[MM*CC];
__device__ float g_attn[MM*CC];
__device__ float g_proj[MM*CC];
__device__ float g_rmean[BB*CC];
__device__ float g_tmph[BB*CH];
__device__ float g_temp[BB*HH];

// ---------------- reductions ----------------
__device__ __forceinline__ float2 block_reduce2(float a, float b) {
    __shared__ float sa[33], sb[33];
    int lane = threadIdx.x & 31, w = threadIdx.x >> 5;
#pragma unroll
    for (int o = 16; o; o >>= 1) {
        a += __shfl_xor_sync(0xffffffffu, a, o);
        b += __shfl_xor_sync(0xffffffffu, b, o);
    }
    if (lane == 0) { sa[w] = a; sb[w] = b; }
    __syncthreads();
    if (w == 0) {
        int nw = (blockDim.x + 31) >> 5;
        a = (lane < nw) ? sa[lane] : 0.f;
        b = (lane < nw) ? sb[lane] : 0.f;
#pragma unroll
        for (int o = 16; o; o >>= 1) {
            a += __shfl_xor_sync(0xffffffffu, a, o);
            b += __shfl_xor_sync(0xffffffffu, b, o);
        }
        if (lane == 0) { sa[32] = a; sb[32] = b; }
    }
    __syncthreads();
    return make_float2(sa[32], sb[32]);
}

__device__ __forceinline__ float block_reduce1(float a) {
    __shared__ float sa[33];
    int lane = threadIdx.x & 31, w = threadIdx.x >> 5;
#pragma unroll
    for (int o = 16; o; o >>= 1) a += __shfl_xor_sync(0xffffffffu, a, o);
    if (lane == 0) sa[w] = a;
    __syncthreads();
    if (w == 0) {
        int nw = (blockDim.x + 31) >> 5;
        a = (lane < nw) ? sa[lane] : 0.f;
#pragma unroll
        for (int o = 16; o; o >>= 1) a += __shfl_xor_sync(0xffffffffu, a, o);
        if (lane == 0) sa[32] = a;
    }
    __syncthreads();
    return sa[32];
}

__device__ __forceinline__ float gelu_exact(float v) {
    return 0.5f * v * (1.f + erff(v * 0.70710678118654752f));
}

// ---------------- 128x128x8 fp32 GEMM: C = A[M,K] @ W[K,N] + bias ----------
__global__ __launch_bounds__(256) void gemm128(
        const float* __restrict__ A, const float* __restrict__ W,
        const float* __restrict__ bias, float* __restrict__ Cout,
        int M, int N, int K) {
    __shared__ float As[8][128];
    __shared__ float Bs[8][128];
    int bm = blockIdx.y * 128, bn = blockIdx.x * 128;
    int t = threadIdx.x;
    int tx = t & 15, ty = t >> 4;

    float acc[8][8];
#pragma unroll
    for (int i = 0; i < 8; i++)
#pragma unroll
        for (int j = 0; j < 8; j++) acc[i][j] = 0.f;

    int arow = t >> 1;
    int acol = (t & 1) * 4;
    const float* Aptr = A + (size_t)(bm + arow) * K + acol;
    int brow = t >> 5;
    int bcol = (t & 31) * 4;
    const float* Wptr = W + (size_t)brow * N + bn + bcol;

    for (int k0 = 0; k0 < K; k0 += 8) {
        float4 av = *(const float4*)(Aptr + k0);
        As[acol + 0][arow] = av.x;
        As[acol + 1][arow] = av.y;
        As[acol + 2][arow] = av.z;
        As[acol + 3][arow] = av.w;
        float4 bv = *(const float4*)(Wptr + (size_t)k0 * N);
        *(float4*)&Bs[brow][bcol] = bv;
        __syncthreads();
#pragma unroll
        for (int kk = 0; kk < 8; kk++) {
            float4 a0 = *(const float4*)&As[kk][ty * 4];
            float4 a1 = *(const float4*)&As[kk][64 + ty * 4];
            float4 b0 = *(const float4*)&Bs[kk][tx * 4];
            float4 b1 = *(const float4*)&Bs[kk][64 + tx * 4];
            float ar[8] = {a0.x, a0.y, a0.z, a0.w, a1.x, a1.y, a1.z, a1.w};
            float br[8] = {b0.x, b0.y, b0.z, b0.w, b1.x, b1.y, b1.z, b1.w};
#pragma unroll
            for (int i = 0; i < 8; i++)
#pragma unroll
                for (int j = 0; j < 8; j++) acc[i][j] += ar[i] * br[j];
        }
        __syncthreads();
    }

#pragma unroll
    for (int i = 0; i < 8; i++) {
        int row = bm + ((i < 4) ? (ty * 4 + i) : (64 + ty * 4 + (i - 4)));
#pragma unroll
        for (int jh = 0; jh < 2; jh++) {
            int col = bn + ((jh == 0) ? (tx * 4) : (64 + tx * 4));
            float4 o;
            o.x = acc[i][jh * 4 + 0] + bias[col + 0];
            o.y = acc[i][jh * 4 + 1] + bias[col + 1];
            o.z = acc[i][jh * 4 + 2] + bias[col + 2];
            o.w = acc[i][jh * 4 + 3] + bias[col + 3];
            *(float4*)&Cout[(size_t)row * N + col] = o;
        }
    }
}

// ---------------- LayerNorm (+ optional exact GELU), in place, per row -----
__global__ void ln_act(float* __restrict__ buf, const float* __restrict__ g,
                       const float* __restrict__ beta, int N, int do_gelu) {
    int row = blockIdx.x;
    float* p = buf + (size_t)row * N;
    float s = 0.f, ss = 0.f;
    for (int c = threadIdx.x; c < N; c += blockDim.x) {
        float v = p[c];
        s += v; ss += v * v;
    }
    float2 r = block_reduce2(s, ss);
    float mean = r.x / N;
    float var = r.y / N - mean * mean;
    float inv = rsqrtf(var + 1e-5f);
    for (int c = threadIdx.x; c < N; c += blockDim.x) {
        float v = (p[c] - mean) * inv * g[c] + beta[c];
        if (do_gelu) v = gelu_exact(v);
        p[c] = v;
    }
}

// ---------------- importance scalar + xi = x * importance ------------------
__global__ void importance_xi(const float* __restrict__ h1,
                              const float* __restrict__ w2,
                              const float* __restrict__ b2,
                              const float* __restrict__ x,
                              float* __restrict__ xi) {
    int row = blockIdx.x;
    const float* hp = h1 + (size_t)row * CH;
    float s = 0.f;
    for (int c = threadIdx.x; c < CH; c += blockDim.x) s += hp[c] * w2[c];
    float tot = block_reduce1(s);
    float v = tot + b2[0];
    float sg = 1.f / (1.f + expf(-v));
    float im = fmaxf(sg, 1e-6f);
    const float* xp = x + (size_t)row * CC;
    float* xop = xi + (size_t)row * CC;
    for (int c = threadIdx.x; c < CC; c += blockDim.x) xop[c] = xp[c] * im;
}

// ---------------- mean over T: reasoned[B,T,C] -> [B,C] --------------------
__global__ void mean_t(const float* __restrict__ r, float* __restrict__ out) {
    int b = blockIdx.y;
    int c = blockIdx.x * 256 + threadIdx.x;
    float s = 0.f;
    for (int t = 0; t < TT; t++) s += r[((size_t)b * TT + t) * CC + c];
    out[b * CC + c] = s * (1.f / TT);
}

// ---------------- tiny GEMM: one block per output element ------------------
__global__ void small_gemm(const float* __restrict__ A, const float* __restrict__ W,
                           const float* __restrict__ bias, float* __restrict__ out,
                           int K, int N) {
    int n = blockIdx.x, m = blockIdx.y;
    float s = 0.f;
    for (int k = threadIdx.x; k < K; k += blockDim.x)
        s += A[(size_t)m * K + k] * W[(size_t)k * N + n];
    float tot = block_reduce1(s);
    if (threadIdx.x == 0) out[m * N + n] = tot + bias[n];
}

__global__ void softplus_k(float* t, int n) {
    int i = threadIdx.x;
    if (i < n) {
        float x = t[i];
        float sp = (x > 20.f) ? x : log1pf(expf(x));
        t[i] = sp + 0.5f;
    }
}

// ---------------- flash attention, fp32 ------------------------------------
// grid (T/32, H, B), block 256 = 8 warps; each warp owns 4 query rows.
__global__ __launch_bounds__(256) void attn_kernel(
        const float* __restrict__ Q, const float* __restrict__ Kt,
        const float* __restrict__ V, const int* __restrict__ mask,
        const float* __restrict__ temp, float* __restrict__ Out) {
    __shared__ float Qs[32][64];
    __shared__ float Ks[32][64];   // rotation-swizzled columns
    __shared__ float Vs[32][64];
    __shared__ float Ps[8][4][32];

    int b = blockIdx.z, h = blockIdx.y;
    int q0 = blockIdx.x * 32;
    int t = threadIdx.x, lane = t & 31, w = t >> 5;
    const size_t base = ((size_t)b * TT) * CC + h * DD;

    // load Q tile (32x64)
#pragma unroll
    for (int i = 0; i < 2; i++) {
        int e = t + i * 256;
        int row = e >> 4, c4 = e & 15;
        *(float4*)&Qs[row][c4 * 4] =
            *(const float4*)&Q[base + (size_t)(q0 + row) * CC + c4 * 4];
    }
    float tmpv = temp[b * HH + h];
    const float scale = 0.125f;  // 1/sqrt(64)

    float m[4], l[4], o0[4], o1[4];
#pragma unroll
    for (int r = 0; r < 4; r++) { m[r] = -INFINITY; l[r] = 0.f; o0[r] = 0.f; o1[r] = 0.f; }

    for (int k0 = 0; k0 < TT; k0 += 32) {
        // load K (swizzled) and V tiles
#pragma unroll
        for (int i = 0; i < 2; i++) {
            int e = t + i * 256;
            int row = e >> 4, c4 = e & 15;
            int pc4 = (c4 + row) & 15;
            *(float4*)&Ks[row][pc4 * 4] =
                *(const float4*)&Kt[base + (size_t)(k0 + row) * CC + c4 * 4];
            *(float4*)&Vs[row][c4 * 4] =
                *(const float4*)&V[base + (size_t)(k0 + row) * CC + c4 * 4];
        }
        __syncthreads();

        // scores: lane j handles key k0+j for rows w*4..w*4+3
        float s[4] = {0.f, 0.f, 0.f, 0.f};
#pragma unroll
        for (int d4 = 0; d4 < 16; d4++) {
            float4 kv = *(const float4*)&Ks[lane][((d4 + lane) & 15) * 4];
#pragma unroll
            for (int r = 0; r < 4; r++) {
                float4 qv = *(const float4*)&Qs[w * 4 + r][d4 * 4];
                s[r] += qv.x * kv.x + qv.y * kv.y + qv.z * kv.z + qv.w * kv.w;
            }
        }

        int kj = k0 + lane;
#pragma unroll
        for (int r = 0; r < 4; r++) {
            int qrow = q0 + w * 4 + r;
            float sv = s[r] * scale * tmpv;
            if (mask[((size_t)b * TT + qrow) * TT + kj] == 0) sv = -INFINITY;
            // warp max
            float mx = sv;
#pragma unroll
            for (int o = 16; o; o >>= 1) mx = fmaxf(mx, __shfl_xor_sync(0xffffffffu, mx, o));
            float mnew = fmaxf(m[r], mx);
            float alpha, p;
            if (mnew == -INFINITY) { alpha = 1.f; p = 0.f; }
            else {
                alpha = __expf(m[r] - mnew);
                p = (sv == -INFINITY) ? 0.f : __expf(sv - mnew);
            }
            m[r] = mnew;
            float ps = p;
#pragma unroll
            for (int o = 16; o; o >>= 1) ps += __shfl_xor_sync(0xffffffffu, ps, o);
            l[r] = l[r] * alpha + ps;
            o0[r] *= alpha; o1[r] *= alpha;
            Ps[w][r][lane] = p;
        }
        __syncwarp();

        // o += P @ V
#pragma unroll 4
        for (int j = 0; j < 32; j++) {
            float vlo = Vs[j][lane];
            float vhi = Vs[j][lane + 32];
#pragma unroll
            for (int r = 0; r < 4; r++) {
                float pj = Ps[w][r][j];
                o0[r] += pj * vlo;
                o1[r] += pj * vhi;
            }
        }
        __syncthreads();
    }

#pragma unroll
    for (int r = 0; r < 4; r++) {
        float inv = 1.f / l[r];
        int qrow = q0 + w * 4 + r;
        Out[base + (size_t)qrow * CC + lane] = o0[r] * inv;
        Out[base + (size_t)qrow * CC + lane + 32] = o1[r] * inv;
    }
}

// ---------------- final residual + LayerNorm -------------------------------
__global__ void final_ln(const float* __restrict__ x, const float* __restrict__ pr,
                         const float* __restrict__ g, const float* __restrict__ be,
                         float* __restrict__ out) {
    int row = blockIdx.x;
    const float* xp = x + (size_t)row * CC;
    const float* pp = pr + (size_t)row * CC;
    float vals[4];
    float s = 0.f, ss = 0.f;
#pragma unroll
    for (int i = 0; i < 4; i++) {
        int c = threadIdx.x + i * 256;
        float v = xp[c] + pp[c];
        vals[i] = v;
        s += v; ss += v * v;
    }
    float2 r = block_reduce2(s, ss);
    float mean = r.x / CC;
    float var = r.y / CC - mean * mean;
    float inv = rsqrtf(var + 1e-5f);
#pragma unroll
    for (int i = 0; i < 4; i++) {
        int c = threadIdx.x + i * 256;
        out[(size_t)row * CC + c] = (vals[i] - mean) * inv * g[c] + be[c];
    }
}

// ---------------- host orchestration ---------------------------------------
extern "C" void kernel_launch(void* const* d_in, const int* in_sizes, int n_in,
                              void* d_out, int out_size) {
    const float* x        = (const float*)d_in[0];
    const int*   amask    = (const int*)d_in[1];
    const float* imp_w1   = (const float*)d_in[2];
    const float* imp_b1   = (const float*)d_in[3];
    const float* imp_g    = (const float*)d_in[4];
    const float* imp_beta = (const float*)d_in[5];
    const float* imp_w2   = (const float*)d_in[6];
    const float* imp_b2   = (const float*)d_in[7];
    const float* rsn_w1   = (const float*)d_in[8];
    const float* rsn_b1   = (const float*)d_in[9];
    const float* rsn_g    = (const float*)d_in[10];
    const float* rsn_beta = (const float*)d_in[11];
    const float* rsn_w2   = (const float*)d_in[12];
    const float* rsn_b2   = (const float*)d_in[13];
    const float* q_w      = (const float*)d_in[14];
    const float* q_b      = (const float*)d_in[15];
    const float* k_w      = (const float*)d_in[16];
    const float* k_b      = (const float*)d_in[17];
    const float* v_w      = (const float*)d_in[18];
    const float* v_b      = (const float*)d_in[19];
    const float* o_w      = (const float*)d_in[20];
    const float* o_b      = (const float*)d_in[21];
    const float* tmp_w1   = (const float*)d_in[22];
    const float* tmp_b1   = (const float*)d_in[23];
    const float* tmp_g    = (const float*)d_in[24];
    const float* tmp_beta = (const float*)d_in[25];
    const float* tmp_w2   = (const float*)d_in[26];
    const float* tmp_b2   = (const float*)d_in[27];
    const float* norm_g   = (const float*)d_in[28];
    const float* norm_b   = (const float*)d_in[29];

    float *p_h1, *p_xi, *p_rsnh, *p_rsn, *p_q, *p_k, *p_v, *p_at, *p_pr;
    float *p_rm, *p_th, *p_tp;
    cudaGetSymbolAddress((void**)&p_h1,  g_h1);
    cudaGetSymbolAddress((void**)&p_xi,  g_xi);
    cudaGetSymbolAddress((void**)&p_rsnh, g_rsnh);
    cudaGetSymbolAddress((void**)&p_rsn, g_reasoned);
    cudaGetSymbolAddress((void**)&p_q,   g_q);
    cudaGetSymbolAddress((void**)&p_k,   g_k);
    cudaGetSymbolAddress((void**)&p_v,   g_v);
    cudaGetSymbolAddress((void**)&p_at,  g_attn);
    cudaGetSymbolAddress((void**)&p_pr,  g_proj);
    cudaGetSymbolAddress((void**)&p_rm,  g_rmean);
    cudaGetSymbolAddress((void**)&p_th,  g_tmph);
    cudaGetSymbolAddress((void**)&p_tp,  g_temp);

    // importance net
    gemm128<<<dim3(CH / 128, MM / 128), 256>>>(x, imp_w1, imp_b1, p_h1, MM, CH, CC);
    ln_act<<<MM, 256>>>(p_h1, imp_g, imp_beta, CH, 1);
    importance_xi<<<MM, 256>>>(p_h1, imp_w2, imp_b2, x, p_xi);

    // reasoning net
    gemm128<<<dim3(CC / 128, MM / 128), 256>>>(p_xi, rsn_w1, rsn_b1, p_rsnh, MM, CC, CC);
    ln_act<<<MM, 256>>>(p_rsnh, rsn_g, rsn_beta, CC, 1);
    gemm128<<<dim3(CC / 128, MM / 128), 256>>>(p_rsnh, rsn_w2, rsn_b2, p_rsn, MM, CC, CC);

    // projections
    gemm128<<<dim3(CC / 128, MM / 128), 256>>>(p_rsn, q_w, q_b, p_q, MM, CC, CC);
    gemm128<<<dim3(CC / 128, MM / 128), 256>>>(p_xi, k_w, k_b, p_k, MM, CC, CC);
    gemm128<<<dim3(CC / 128, MM / 128), 256>>>(x, v_w, v_b, p_v, MM, CC, CC);

    // temperature net
    mean_t<<<dim3(CC / 256, BB), 256>>>(p_rsn, p_rm);
    small_gemm<<<dim3(CH, BB), 128>>>(p_rm, tmp_w1, tmp_b1, p_th, CC, CH);
    ln_act<<<BB, 256>>>(p_th, tmp_g, tmp_beta, CH, 1);
    small_gemm<<<dim3(HH, BB), 128>>>(p_th, tmp_w2, tmp_b2, p_tp, CH, HH);
    softplus_k<<<1, 32>>>(p_tp, BB * HH);

    // attention
    attn_kernel<<<dim3(TT / 32, HH, BB), 256>>>(p_q, p_k, p_v, amask, p_tp, p_at);

    // output projection + residual LN
    gemm128<<<dim3(CC / 128, MM / 128), 256>>>(p_at, o_w, o_b, p_pr, MM, CC, CC);
    final_ln<<<MM, 256>>>(x, p_pr, norm_g, norm_b, (float*)d_out);
}

// round 7
// speedup vs baseline: 1.7805x; 1.7805x over previous
#include <cuda_runtime.h>
#include <cuda_bf16.h>
#include <math.h>
#include <stdint.h>

#define BB 2
#define TT 2048
#define CC 1024
#define HH 16
#define DD 64
#define CH 512
#define MM (BB*TT)

// ---------------- scratch ----------------
__device__ float g_h1[MM*CH];
__device__ float g_xi[MM*CC];
__device__ float g_rsnh[MM*CC];
__device__ float g_rsn[MM*CC];
__device__ float g_q[MM*CC];
__device__ float g_k[MM*CC];
__device__ float g_v[MM*CC];
__device__ float g_at[MM*CC];
__device__ float g_pr[MM*CC];
__device__ float g_rm[BB*CC];
__device__ float g_th[BB*CH];
__device__ float g_tp[BB*HH];
__device__ __align__(16) __nv_bfloat16 g_ah[MM*CC], g_al[MM*CC];
__device__ __align__(16) __nv_bfloat16 g_w1h[CH*CC], g_w1l[CH*CC];
__device__ __align__(16) __nv_bfloat16 g_wh[6][CC*CC], g_wl[6][CC*CC];

// ---------------- helpers ----------------
__device__ __forceinline__ uint32_t smem_u32(const void* p) {
    uint32_t a;
    asm("{ .reg .u64 t; cvta.to.shared.u64 t, %1; cvt.u32.u64 %0, t; }" : "=r"(a) : "l"(p));
    return a;
}
__device__ __forceinline__ void cp16(uint32_t dst, const __nv_bfloat16* src) {
    asm volatile("cp.async.cg.shared.global [%0], [%1], 16;"
                 :: "r"(dst), "l"(__cvta_generic_to_global(src)));
}
__device__ __forceinline__ void cp_commit() {
    asm volatile("cp.async.commit_group;");
}
__device__ __forceinline__ void mma_bf16(float* c, const uint32_t* a, const uint32_t* b) {
    asm volatile(
        "mma.sync.aligned.m16n8k16.row.col.f32.bf16.bf16.f32 "
        "{%0,%1,%2,%3}, {%4,%5,%6,%7}, {%8,%9}, {%0,%1,%2,%3};"
        : "+f"(c[0]), "+f"(c[1]), "+f"(c[2]), "+f"(c[3])
        : "r"(a[0]), "r"(a[1]), "r"(a[2]), "r"(a[3]), "r"(b[0]), "r"(b[1]));
}

// ---------------- HMMA bf16x3 GEMM: C[M,N] = A @ W + bias ------------------
// A split (Ah,Al)[M][K] row-major; B split (Bh,Bl)[N][K] = W^T row-major.
// CTA tile 128x128, warp tile 32x64, K-chunk 32, cp.async double buffered.
// smem per stage: Ah,Al,Bh,Bl each 128 rows x 20 words (stride pad) = 10240B.
#define STG_BYTES 40960
__global__ __launch_bounds__(256) void gemm_mma(
        const __nv_bfloat16* __restrict__ Ah, const __nv_bfloat16* __restrict__ Al,
        const __nv_bfloat16* __restrict__ Bh, const __nv_bfloat16* __restrict__ Bl,
        const float* __restrict__ bias, float* __restrict__ Cc,
        int M, int N, int K) {
    extern __shared__ __align__(16) char dsm[];
    const int t = threadIdx.x;
    const int lane = t & 31, w = t >> 5;
    const int wm = w & 3, wn = w >> 2;       // 4 row-warps x 2 col-warps
    const int g = lane >> 2;                  // 0..7
    const int m0 = blockIdx.y * 128, n0 = blockIdx.x * 128;
    const uint32_t smb = smem_u32(dsm);

    float acc[2][8][4];
#pragma unroll
    for (int mt = 0; mt < 2; mt++)
#pragma unroll
        for (int nt = 0; nt < 8; nt++)
#pragma unroll
            for (int i = 0; i < 4; i++) acc[mt][nt][i] = 0.f;

    const __nv_bfloat16* base_ptr[4] = {
        Ah + (size_t)m0 * K, Al + (size_t)m0 * K,
        Bh + (size_t)n0 * K, Bl + (size_t)n0 * K };

    const int nch = K >> 5;
    // prologue: load chunk 0 into stage 0
    {
        const int k0 = 0;
#pragma unroll
        for (int i = 0; i < 8; i++) {
            int arr = i >> 1;
            int rem = t + (i & 1) * 256;
            int row = rem >> 2, c = rem & 3;
            cp16(smb + arr * 10240 + row * 80 + c * 16,
                 base_ptr[arr] + (size_t)row * K + k0 + c * 8);
        }
        cp_commit();
    }

    for (int ch = 0; ch < nch; ch++) {
        const int stage = ch & 1;
        if (ch + 1 < nch) {
            const int k0 = (ch + 1) << 5;
            const uint32_t sb = smb + (stage ^ 1) * STG_BYTES;
#pragma unroll
            for (int i = 0; i < 8; i++) {
                int arr = i >> 1;
                int rem = t + (i & 1) * 256;
                int row = rem >> 2, c = rem & 3;
                cp16(sb + arr * 10240 + row * 80 + c * 16,
                     base_ptr[arr] + (size_t)row * K + k0 + c * 8);
            }
            cp_commit();
            asm volatile("cp.async.wait_group 1;");
        } else {
            asm volatile("cp.async.wait_group 0;");
        }
        __syncthreads();

        const uint32_t* Ah_s = (const uint32_t*)(dsm + stage * STG_BYTES);
        const uint32_t* Al_s = Ah_s + 2560;
        const uint32_t* Bh_s = Ah_s + 5120;
        const uint32_t* Bl_s = Ah_s + 7680;

#pragma unroll
        for (int ks = 0; ks < 2; ks++) {
            const int w0 = ks * 8 + (lane & 3);
            uint32_t AH[2][4], AL[2][4];
#pragma unroll
            for (int mt = 0; mt < 2; mt++) {
                int rb = (wm * 32 + mt * 16 + g) * 20;
                AH[mt][0] = Ah_s[rb + w0];
                AH[mt][1] = Ah_s[rb + 160 + w0];
                AH[mt][2] = Ah_s[rb + w0 + 4];
                AH[mt][3] = Ah_s[rb + 160 + w0 + 4];
                AL[mt][0] = Al_s[rb + w0];
                AL[mt][1] = Al_s[rb + 160 + w0];
                AL[mt][2] = Al_s[rb + w0 + 4];
                AL[mt][3] = Al_s[rb + 160 + w0 + 4];
            }
#pragma unroll
            for (int nt = 0; nt < 8; nt++) {
                int cb = (wn * 64 + nt * 8 + g) * 20;
                uint32_t BH[2], BL[2];
                BH[0] = Bh_s[cb + w0]; BH[1] = Bh_s[cb + w0 + 4];
                BL[0] = Bl_s[cb + w0]; BL[1] = Bl_s[cb + w0 + 4];
#pragma unroll
                for (int mt = 0; mt < 2; mt++) {
                    mma_bf16(acc[mt][nt], AH[mt], BH);
                    mma_bf16(acc[mt][nt], AH[mt], BL);
                    mma_bf16(acc[mt][nt], AL[mt], BH);
                }
            }
        }
        __syncthreads();
    }

    // epilogue: direct global stores (float2), + bias
#pragma unroll
    for (int mt = 0; mt < 2; mt++) {
        int row0 = m0 + wm * 32 + mt * 16 + g;
#pragma unroll
        for (int nt = 0; nt < 8; nt++) {
            int col = n0 + wn * 64 + nt * 8 + (lane & 3) * 2;
            float2 bz = *(const float2*)&bias[col];
            float2 v0 = make_float2(acc[mt][nt][0] + bz.x, acc[mt][nt][1] + bz.y);
            float2 v1 = make_float2(acc[mt][nt][2] + bz.x, acc[mt][nt][3] + bz.y);
            *(float2*)&Cc[(size_t)row0 * N + col] = v0;
            *(float2*)&Cc[(size_t)(row0 + 8) * N + col] = v1;
        }
    }
}

// ---------------- reductions / misc ----------------
__device__ __forceinline__ float2 block_reduce2(float a, float b) {
    __shared__ float sa[33], sb[33];
    int lane = threadIdx.x & 31, w = threadIdx.x >> 5;
#pragma unroll
    for (int o = 16; o; o >>= 1) {
        a += __shfl_xor_sync(~0u, a, o);
        b += __shfl_xor_sync(~0u, b, o);
    }
    if (lane == 0) { sa[w] = a; sb[w] = b; }
    __syncthreads();
    if (w == 0) {
        int nw = (blockDim.x + 31) >> 5;
        a = (lane < nw) ? sa[lane] : 0.f;
        b = (lane < nw) ? sb[lane] : 0.f;
#pragma unroll
        for (int o = 16; o; o >>= 1) {
            a += __shfl_xor_sync(~0u, a, o);
            b += __shfl_xor_sync(~0u, b, o);
        }
        if (lane == 0) { sa[32] = a; sb[32] = b; }
    }
    __syncthreads();
    return make_float2(sa[32], sb[32]);
}
__device__ __forceinline__ float block_reduce1(float a) {
    __shared__ float sa[33];
    int lane = threadIdx.x & 31, w = threadIdx.x >> 5;
#pragma unroll
    for (int o = 16; o; o >>= 1) a += __shfl_xor_sync(~0u, a, o);
    if (lane == 0) sa[w] = a;
    __syncthreads();
    if (w == 0) {
        int nw = (blockDim.x + 31) >> 5;
        a = (lane < nw) ? sa[lane] : 0.f;
#pragma unroll
        for (int o = 16; o; o >>= 1) a += __shfl_xor_sync(~0u, a, o);
        if (lane == 0) sa[32] = a;
    }
    __syncthreads();
    return sa[32];
}
__device__ __forceinline__ float gelu_exact(float v) {
    return 0.5f * v * (1.f + erff(v * 0.70710678118654752f));
}

__global__ void asplit(const float* __restrict__ src, __nv_bfloat16* __restrict__ hi,
                       __nv_bfloat16* __restrict__ lo, int n4) {
    int i = blockIdx.x * 256 + threadIdx.x;
    if (i >= n4) return;
    float4 v = ((const float4*)src)[i];
    __nv_bfloat162 h0, h1, l0, l1;
    h0.x = __float2bfloat16(v.x); h0.y = __float2bfloat16(v.y);
    h1.x = __float2bfloat16(v.z); h1.y = __float2bfloat16(v.w);
    l0.x = __float2bfloat16(v.x - __bfloat162float(h0.x));
    l0.y = __float2bfloat16(v.y - __bfloat162float(h0.y));
    l1.x = __float2bfloat16(v.z - __bfloat162float(h1.x));
    l1.y = __float2bfloat16(v.w - __bfloat162float(h1.y));
    ((__nv_bfloat162*)hi)[i*2] = h0; ((__nv_bfloat162*)hi)[i*2+1] = h1;
    ((__nv_bfloat162*)lo)[i*2] = l0; ((__nv_bfloat162*)lo)[i*2+1] = l1;
}

__global__ void wsplit(const float* __restrict__ W, __nv_bfloat16* __restrict__ Th,
                       __nv_bfloat16* __restrict__ Tl, int K, int N) {
    __shared__ float tile[32][33];
    int k0 = blockIdx.y * 32, n0 = blockIdx.x * 32;
    int tx = threadIdx.x, ty = threadIdx.y;
#pragma unroll
    for (int i = ty; i < 32; i += 8)
        tile[i][tx] = W[(size_t)(k0 + i) * N + n0 + tx];
    __syncthreads();
#pragma unroll
    for (int i = ty; i < 32; i += 8) {
        float v = tile[tx][i];
        __nv_bfloat16 h = __float2bfloat16(v);
        Th[(size_t)(n0 + i) * K + k0 + tx] = h;
        Tl[(size_t)(n0 + i) * K + k0 + tx] = __float2bfloat16(v - __bfloat162float(h));
    }
}

__global__ void ln_act(float* __restrict__ buf, const float* __restrict__ g,
                       const float* __restrict__ beta, int N, int do_gelu) {
    int row = blockIdx.x;
    float* p = buf + (size_t)row * N;
    float s = 0.f, ss = 0.f;
    for (int c = threadIdx.x; c < N; c += blockDim.x) {
        float v = p[c];
        s += v; ss += v * v;
    }
    float2 r = block_reduce2(s, ss);
    float mean = r.x / N;
    float inv = rsqrtf(r.y / N - mean * mean + 1e-5f);
    for (int c = threadIdx.x; c < N; c += blockDim.x) {
        float v = (p[c] - mean) * inv * g[c] + beta[c];
        if (do_gelu) v = gelu_exact(v);
        p[c] = v;
    }
}

__global__ void importance_xi(const float* __restrict__ h1, const float* __restrict__ w2,
                              const float* __restrict__ b2, const float* __restrict__ x,
                              float* __restrict__ xi) {
    int row = blockIdx.x;
    const float* hp = h1 + (size_t)row * CH;
    float s = 0.f;
    for (int c = threadIdx.x; c < CH; c += blockDim.x) s += hp[c] * w2[c];
    float tot = block_reduce1(s);
    float im = fmaxf(1.f / (1.f + expf(-(tot + b2[0]))), 1e-6f);
    const float* xp = x + (size_t)row * CC;
    float* xop = xi + (size_t)row * CC;
    for (int c = threadIdx.x; c < CC; c += blockDim.x) xop[c] = xp[c] * im;
}

__global__ void mean_t(const float* __restrict__ r, float* __restrict__ out) {
    int c = blockIdx.x * 32 + threadIdx.x;
    int b = blockIdx.y;
    float s = 0.f;
    for (int tt = threadIdx.y; tt < TT; tt += 8)
        s += r[((size_t)b * TT + tt) * CC + c];
    __shared__ float sm[8][33];
    sm[threadIdx.y][threadIdx.x] = s;
    __syncthreads();
    if (threadIdx.y == 0) {
        float acc = 0.f;
#pragma unroll
        for (int i = 0; i < 8; i++) acc += sm[i][threadIdx.x];
        out[b * CC + c] = acc * (1.f / TT);
    }
}

__global__ void small_gemm(const float* __restrict__ A, const float* __restrict__ W,
                           const float* __restrict__ bias, float* __restrict__ out,
                           int K, int N) {
    int n = blockIdx.x, m = blockIdx.y;
    float s = 0.f;
    for (int k = threadIdx.x; k < K; k += blockDim.x)
        s += A[(size_t)m * K + k] * W[(size_t)k * N + n];
    float tot = block_reduce1(s);
    if (threadIdx.x == 0) out[m * N + n] = tot + bias[n];
}

__global__ void softplus_k(float* t, int n) {
    int i = threadIdx.x;
    if (i < n) {
        float x = t[i];
        t[i] = ((x > 20.f) ? x : log1pf(expf(x))) + 0.5f;
    }
}

// ---------------- flash attention fp32, 64q x 32k tiles --------------------
__global__ __launch_bounds__(256) void attn64(
        const float* __restrict__ Q, const float* __restrict__ Kt,
        const float* __restrict__ V, const int* __restrict__ mask,
        const float* __restrict__ temp, float* __restrict__ Out) {
    __shared__ float Qs[64][68];
    __shared__ float Ks[64][34];
    __shared__ float Vs[32][68];
    __shared__ float Ps[32][68];

    const int b = blockIdx.z, h = blockIdx.y;
    const int q0 = blockIdx.x * 64;
    const int t = threadIdx.x, tx = t & 15, ty = t >> 4;
    const size_t base = ((size_t)b * TT) * CC + (size_t)h * DD;

#pragma unroll
    for (int i = 0; i < 4; i++) {
        int e = t + (i << 8);
        int row = e >> 4, k4 = e & 15;
        float4 v = *(const float4*)&Q[base + (size_t)(q0 + row) * CC + (k4 << 2)];
        Qs[k4*4+0][row] = v.x; Qs[k4*4+1][row] = v.y;
        Qs[k4*4+2][row] = v.z; Qs[k4*4+3][row] = v.w;
    }
    const float st = 0.125f * temp[b * HH + h];

    float m[4], l[4], o[4][4];
#pragma unroll
    for (int r = 0; r < 4; r++) {
        m[r] = -INFINITY; l[r] = 0.f;
#pragma unroll
        for (int d = 0; d < 4; d++) o[r][d] = 0.f;
    }
    const int qrow0 = q0 + ty * 4;
    __syncthreads();

    for (int k0 = 0; k0 < TT; k0 += 32) {
#pragma unroll
        for (int i = 0; i < 2; i++) {
            int e = t + (i << 8);
            int kr = e >> 4, k4 = e & 15;
            float4 kv = *(const float4*)&Kt[base + (size_t)(k0 + kr) * CC + (k4 << 2)];
            Ks[k4*4+0][kr] = kv.x; Ks[k4*4+1][kr] = kv.y;
            Ks[k4*4+2][kr] = kv.z; Ks[k4*4+3][kr] = kv.w;
            *(float4*)&Vs[kr][k4 << 2] =
                *(const float4*)&V[base + (size_t)(k0 + kr) * CC + (k4 << 2)];
        }
        __syncthreads();

        float s[4][2];
#pragma unroll
        for (int r = 0; r < 4; r++) { s[r][0] = 0.f; s[r][1] = 0.f; }
#pragma unroll 8
        for (int dk = 0; dk < 64; dk++) {
            float4 q4 = *(const float4*)&Qs[dk][ty * 4];
            float2 k2 = *(const float2*)&Ks[dk][tx * 2];
            s[0][0] += q4.x * k2.x; s[0][1] += q4.x * k2.y;
            s[1][0] += q4.y * k2.x; s[1][1] += q4.y * k2.y;
            s[2][0] += q4.z * k2.x; s[2][1] += q4.z * k2.y;
            s[3][0] += q4.w * k2.x; s[3][1] += q4.w * k2.y;
        }

#pragma unroll
        for (int r = 0; r < 4; r++) {
            int2 mv = *(const int2*)&mask[((size_t)b*TT + (qrow0+r))*TT + k0 + tx*2];
            float sv0 = (mv.x == 0) ? -INFINITY : s[r][0] * st;
            float sv1 = (mv.y == 0) ? -INFINITY : s[r][1] * st;
            float mx = fmaxf(sv0, sv1);
#pragma unroll
            for (int off = 8; off; off >>= 1)
                mx = fmaxf(mx, __shfl_xor_sync(~0u, mx, off));
            float mnew = fmaxf(m[r], mx);
            float alpha, p0, p1;
            if (mnew == -INFINITY) { alpha = 1.f; p0 = 0.f; p1 = 0.f; }
            else {
                alpha = __expf(m[r] - mnew);
                p0 = (sv0 == -INFINITY) ? 0.f : __expf(sv0 - mnew);
                p1 = (sv1 == -INFINITY) ? 0.f : __expf(sv1 - mnew);
            }
            m[r] = mnew;
            float ps = p0 + p1;
#pragma unroll
            for (int off = 8; off; off >>= 1)
                ps += __shfl_xor_sync(~0u, ps, off);
            l[r] = l[r] * alpha + ps;
#pragma unroll
            for (int d = 0; d < 4; d++) o[r][d] *= alpha;
            Ps[tx*2+0][ty*4+r] = p0;
            Ps[tx*2+1][ty*4+r] = p1;
        }
        __syncthreads();

#pragma unroll 4
        for (int kk = 0; kk < 32; kk++) {
            float4 p4 = *(const float4*)&Ps[kk][ty * 4];
            float4 v4 = *(const float4*)&Vs[kk][tx * 4];
            o[0][0] += p4.x*v4.x; o[0][1] += p4.x*v4.y; o[0][2] += p4.x*v4.z; o[0][3] += p4.x*v4.w;
            o[1][0] += p4.y*v4.x; o[1][1] += p4.y*v4.y; o[1][2] += p4.y*v4.z; o[1][3] += p4.y*v4.w;
            o[2][0] += p4.z*v4.x; o[2][1] += p4.z*v4.y; o[2][2] += p4.z*v4.z; o[2][3] += p4.z*v4.w;
            o[3][0] += p4.w*v4.x; o[3][1] += p4.w*v4.y; o[3][2] += p4.w*v4.z; o[3][3] += p4.w*v4.w;
        }
        __syncthreads();
    }

#pragma unroll
    for (int r = 0; r < 4; r++) {
        float inv = 1.f / l[r];
        float4 res = make_float4(o[r][0]*inv, o[r][1]*inv, o[r][2]*inv, o[r][3]*inv);
        *(float4*)&Out[base + (size_t)(qrow0 + r) * CC + tx * 4] = res;
    }
}

__global__ void final_ln(const float* __restrict__ x, const float* __restrict__ pr,
                         const float* __restrict__ g, const float* __restrict__ be,
                         float* __restrict__ out) {
    int row = blockIdx.x;
    const float* xp = x + (size_t)row * CC;
    const float* pp = pr + (size_t)row * CC;
    float vals[4];
    float s = 0.f, ss = 0.f;
#pragma unroll
    for (int i = 0; i < 4; i++) {
        int c = threadIdx.x + i * 256;
        float v = xp[c] + pp[c];
        vals[i] = v; s += v; ss += v * v;
    }
    float2 r = block_reduce2(s, ss);
    float mean = r.x / CC;
    float inv = rsqrtf(r.y / CC - mean * mean + 1e-5f);
#pragma unroll
    for (int i = 0; i < 4; i++) {
        int c = threadIdx.x + i * 256;
        out[(size_t)row * CC + c] = (vals[i] - mean) * inv * g[c] + be[c];
    }
}

// ---------------- host ----------------
extern "C" void kernel_launch(void* const* d_in, const int* in_sizes, int n_in,
                              void* d_out, int out_size) {
    const float* x        = (const float*)d_in[0];
    const int*   amask    = (const int*)d_in[1];
    const float* imp_w1   = (const float*)d_in[2];
    const float* imp_b1   = (const float*)d_in[3];
    const float* imp_g    = (const float*)d_in[4];
    const float* imp_beta = (const float*)d_in[5];
    const float* imp_w2   = (const float*)d_in[6];
    const float* imp_b2   = (const float*)d_in[7];
    const float* rsn_w1   = (const float*)d_in[8];
    const float* rsn_b1   = (const float*)d_in[9];
    const float* rsn_g    = (const float*)d_in[10];
    const float* rsn_beta = (const float*)d_in[11];
    const float* rsn_w2   = (const float*)d_in[12];
    const float* rsn_b2   = (const float*)d_in[13];
    const float* q_w      = (const float*)d_in[14];
    const float* q_b      = (const float*)d_in[15];
    const float* k_w      = (const float*)d_in[16];
    const float* k_b      = (const float*)d_in[17];
    const float* v_w      = (const float*)d_in[18];
    const float* v_b      = (const float*)d_in[19];
    const float* o_w      = (const float*)d_in[20];
    const float* o_b      = (const float*)d_in[21];
    const float* tmp_w1   = (const float*)d_in[22];
    const float* tmp_b1   = (const float*)d_in[23];
    const float* tmp_g    = (const float*)d_in[24];
    const float* tmp_beta = (const float*)d_in[25];
    const float* tmp_w2   = (const float*)d_in[26];
    const float* tmp_b2   = (const float*)d_in[27];
    const float* norm_g   = (const float*)d_in[28];
    const float* norm_b   = (const float*)d_in[29];

    float *p_h1,*p_xi,*p_rsnh,*p_rsn,*p_q,*p_k,*p_v,*p_at,*p_pr,*p_rm,*p_th,*p_tp;
    __nv_bfloat16 *p_ah,*p_al,*p_w1h,*p_w1l,*p_wh,*p_wl;
    cudaGetSymbolAddress((void**)&p_h1, g_h1);
    cudaGetSymbolAddress((void**)&p_xi, g_xi);
    cudaGetSymbolAddress((void**)&p_rsnh, g_rsnh);
    cudaGetSymbolAddress((void**)&p_rsn, g_rsn);
    cudaGetSymbolAddress((void**)&p_q, g_q);
    cudaGetSymbolAddress((void**)&p_k, g_k);
    cudaGetSymbolAddress((void**)&p_v, g_v);
    cudaGetSymbolAddress((void**)&p_at, g_at);
    cudaGetSymbolAddress((void**)&p_pr, g_pr);
    cudaGetSymbolAddress((void**)&p_rm, g_rm);
    cudaGetSymbolAddress((void**)&p_th, g_th);
    cudaGetSymbolAddress((void**)&p_tp, g_tp);
    cudaGetSymbolAddress((void**)&p_ah, g_ah);
    cudaGetSymbolAddress((void**)&p_al, g_al);
    cudaGetSymbolAddress((void**)&p_w1h, g_w1h);
    cudaGetSymbolAddress((void**)&p_w1l, g_w1l);
    cudaGetSymbolAddress((void**)&p_wh, g_wh);
    cudaGetSymbolAddress((void**)&p_wl, g_wl);
    __nv_bfloat16 *wh[6], *wl[6];
    for (int i = 0; i < 6; i++) { wh[i] = p_wh + (size_t)i*CC*CC; wl[i] = p_wl + (size_t)i*CC*CC; }

    cudaFuncSetAttribute(gemm_mma, cudaFuncAttributeMaxDynamicSharedMemorySize, 2 * STG_BYTES);
    const int GSM = 2 * STG_BYTES;
    const int n4 = MM * CC / 4;
    dim3 wsb(32, 8);

    // weight transposes + splits
    wsplit<<<dim3(CC/32, CC/32), wsb>>>(rsn_w1, wh[0], wl[0], CC, CC);
    wsplit<<<dim3(CC/32, CC/32), wsb>>>(rsn_w2, wh[1], wl[1], CC, CC);
    wsplit<<<dim3(CC/32, CC/32), wsb>>>(q_w,    wh[2], wl[2], CC, CC);
    wsplit<<<dim3(CC/32, CC/32), wsb>>>(k_w,    wh[3], wl[3], CC, CC);
    wsplit<<<dim3(CC/32, CC/32), wsb>>>(v_w,    wh[4], wl[4], CC, CC);
    wsplit<<<dim3(CC/32, CC/32), wsb>>>(o_w,    wh[5], wl[5], CC, CC);
    wsplit<<<dim3(CH/32, CC/32), wsb>>>(imp_w1, p_w1h, p_w1l, CC, CH);

    // split(x) -> imp1, v
    asplit<<<n4/256, 256>>>(x, p_ah, p_al, n4);
    gemm_mma<<<dim3(CH/128, MM/128), 256, GSM>>>(p_ah, p_al, p_w1h, p_w1l, imp_b1, p_h1, MM, CH, CC);
    gemm_mma<<<dim3(CC/128, MM/128), 256, GSM>>>(p_ah, p_al, wh[4], wl[4], v_b, p_v, MM, CC, CC);

    ln_act<<<MM, 256>>>(p_h1, imp_g, imp_beta, CH, 1);
    importance_xi<<<MM, 256>>>(p_h1, imp_w2, imp_b2, x, p_xi);

    // split(xi) -> rsn1, k
    asplit<<<n4/256, 256>>>(p_xi, p_ah, p_al, n4);
    gemm_mma<<<dim3(CC/128, MM/128), 256, GSM>>>(p_ah, p_al, wh[0], wl[0], rsn_b1, p_rsnh, MM, CC, CC);
    gemm_mma<<<dim3(CC/128, MM/128), 256, GSM>>>(p_ah, p_al, wh[3], wl[3], k_b, p_k, MM, CC, CC);

    ln_act<<<MM, 256>>>(p_rsnh, rsn_g, rsn_beta, CC, 1);
    asplit<<<n4/256, 256>>>(p_rsnh, p_ah, p_al, n4);
    gemm_mma<<<dim3(CC/128, MM/128), 256, GSM>>>(p_ah, p_al, wh[1], wl[1], rsn_b2, p_rsn, MM, CC, CC);

    asplit<<<n4/256, 256>>>(p_rsn, p_ah, p_al, n4);
    gemm_mma<<<dim3(CC/128, MM/128), 256, GSM>>>(p_ah, p_al, wh[2], wl[2], q_b, p_q, MM, CC, CC);

    // temperature net
    mean_t<<<dim3(CC/32, BB), dim3(32, 8)>>>(p_rsn, p_rm);
    small_gemm<<<dim3(CH, BB), 128>>>(p_rm, tmp_w1, tmp_b1, p_th, CC, CH);
    ln_act<<<BB, 256>>>(p_th, tmp_g, tmp_beta, CH, 1);
    small_gemm<<<dim3(HH, BB), 128>>>(p_th, tmp_w2, tmp_b2, p_tp, CH, HH);
    softplus_k<<<1, 32>>>(p_tp, BB * HH);

    // attention
    attn64<<<dim3(TT/64, HH, BB), 256>>>(p_q, p_k, p_v, amask, p_tp, p_at);

    // output projection + residual LN
    asplit<<<n4/256, 256>>>(p_at, p_ah, p_al, n4);
    gemm_mma<<<dim3(CC/128, MM/128), 256, GSM>>>(p_ah, p_al, wh[5], wl[5], o_b, p_pr, MM, CC, CC);
    final_ln<<<MM, 256>>>(x, p_pr, norm_g, norm_b, (float*)d_out);
}